// round 14
// baseline (speedup 1.0000x reference)
#include <cuda_runtime.h>
#include <cuda_bf16.h>
#include <cstdint>

#define N_NODES 50000
#define M_PAD   50048
#define N_EDGES 800000
#define N_GRAPHS 256
#define OUT_CLS 7
#define NEG_SLOPE 0.01f

// Output layout: logits [256*7] | reconstructed [N*1024] | original [N*1024]
#define OFF_RECON (N_GRAPHS * OUT_CLS)
#define OFF_ORIG  (OFF_RECON + N_NODES * 1024)

// ---------------- fp32 scratch ----------------------------------------------------
__device__ float g_h1   [N_NODES * 64];
__device__ float g_enc  [N_NODES * 512];   // fused enc GEMM output: [rel(256) | root(256)]
__device__ float g_lat  [N_NODES * 256];
__device__ float g_pool [N_GRAPHS * 256];
__device__ float g_cnt  [N_GRAPHS];

// ---------------- CSR scratch -----------------------------------------------------
#define SCAN_BLOCKS ((N_NODES + 1023) / 1024)
__device__ int g_deg   [N_NODES];
__device__ int g_rowptr[N_NODES + 1];
__device__ int g_posn  [N_NODES];
__device__ int g_esrc  [N_EDGES];
__device__ int g_part  [SCAN_BLOCKS + 1];

// ---------------- pre-split bf16 scratch (hi/lo), padded rows ---------------------
__device__ __nv_bfloat16 g_h1h [M_PAD * 64];
__device__ __nv_bfloat16 g_h1l [M_PAD * 64];
__device__ __nv_bfloat16 g_a1h [M_PAD * 64];
__device__ __nv_bfloat16 g_a1l [M_PAD * 64];
__device__ __nv_bfloat16 g_oh  [M_PAD * 1024];
__device__ __nv_bfloat16 g_ol  [M_PAD * 1024];
__device__ __nv_bfloat16 g_lath[M_PAD * 256];
__device__ __nv_bfloat16 g_latl[M_PAD * 256];
__device__ __nv_bfloat16 g_aggh[M_PAD * 256];
__device__ __nv_bfloat16 g_aggl[M_PAD * 256];
// transposed weights [N][K] hi/lo
__device__ __nv_bfloat16 g_w2r_h[1024 * 64],  g_w2r_l[1024 * 64];
__device__ __nv_bfloat16 g_w2o_h[1024 * 64],  g_w2o_l[1024 * 64];
__device__ __nv_bfloat16 g_wcat_h[512 * 1024], g_wcat_l[512 * 1024];  // [we_rel ; we_root]
__device__ __nv_bfloat16 g_wdr_h[1024 * 256], g_wdr_l[1024 * 256];
__device__ __nv_bfloat16 g_wdo_h[1024 * 256], g_wdo_l[1024 * 256];

// ---------------- helpers ---------------------------------------------------------
__device__ __forceinline__ void red_add_v4(float4* addr, float4 v) {
    asm volatile("red.global.add.v4.f32 [%0], {%1, %2, %3, %4};"
                 :: "l"(addr), "f"(v.x), "f"(v.y), "f"(v.z), "f"(v.w) : "memory");
}
__device__ __forceinline__ float lrelu(float v) { return v >= 0.f ? v : NEG_SLOPE * v; }

__device__ __forceinline__ uint32_t pack_bf16(float x, float y) {
    __nv_bfloat162 t = __floats2bfloat162_rn(x, y);
    return *reinterpret_cast<uint32_t*>(&t);
}
__device__ __forceinline__ float bf_round(float v) {
    return __bfloat162float(__float2bfloat16(v));
}

__device__ __forceinline__ void mma_bf16(float* d, const uint32_t* a, const uint32_t* b) {
    asm volatile(
        "mma.sync.aligned.m16n8k16.row.col.f32.bf16.bf16.f32 "
        "{%0,%1,%2,%3}, {%4,%5,%6,%7}, {%8,%9}, {%0,%1,%2,%3};"
        : "+f"(d[0]), "+f"(d[1]), "+f"(d[2]), "+f"(d[3])
        : "r"(a[0]), "r"(a[1]), "r"(a[2]), "r"(a[3]), "r"(b[0]), "r"(b[1]));
}

__device__ __forceinline__ void ldsm4(uint32_t* r, uint32_t addr) {
    asm volatile("ldmatrix.sync.aligned.m8n8.x4.shared.b16 {%0,%1,%2,%3}, [%4];"
                 : "=r"(r[0]), "=r"(r[1]), "=r"(r[2]), "=r"(r[3]) : "r"(addr));
}

__device__ __forceinline__ void cp16(uint32_t dst, const void* src) {
    asm volatile("cp.async.cg.shared.global [%0], [%1], 16;" :: "r"(dst), "l"(src));
}
__device__ __forceinline__ void cp_commit() { asm volatile("cp.async.commit_group;"); }
template <int Np> __device__ __forceinline__ void cp_wait() {
    asm volatile("cp.async.wait_group %0;" :: "n"(Np));
}

// ---------------- CSR build -------------------------------------------------------
__global__ void zero_misc(int* deg, float* pool, float* cnt) {
    int i = blockIdx.x * blockDim.x + threadIdx.x;
    if (i < N_NODES) deg[i] = 0;
    if (i < N_GRAPHS * 256) pool[i] = 0.f;
    if (i < N_GRAPHS) cnt[i] = 0.f;
}

__global__ void hist_kernel(const int* __restrict__ dst, int* __restrict__ deg,
                            const int* __restrict__ batch, float* __restrict__ counts) {
    int e = blockIdx.x * blockDim.x + threadIdx.x;
    if (e < N_EDGES) atomicAdd(&deg[dst[e]], 1);
    if (e < N_NODES) atomicAdd(&counts[batch[e]], 1.0f);
}

__global__ void scan_local(const int* __restrict__ deg, int* __restrict__ rowptr,
                           int* __restrict__ part) {
    __shared__ int sh[1024];
    int tid = threadIdx.x;
    int i = blockIdx.x * 1024 + tid;
    int v = (i < N_NODES) ? deg[i] : 0;
    sh[tid] = v;
    __syncthreads();
#pragma unroll
    for (int off = 1; off < 1024; off <<= 1) {
        int t = (tid >= off) ? sh[tid - off] : 0;
        __syncthreads();
        sh[tid] += t;
        __syncthreads();
    }
    if (i < N_NODES) rowptr[i] = sh[tid] - v;
    if (tid == 1023) part[blockIdx.x] = sh[1023];
}

__global__ void scan_partials(int* __restrict__ part) {
    __shared__ int sh[64];
    int tid = threadIdx.x;
    int v = (tid < SCAN_BLOCKS) ? part[tid] : 0;
    sh[tid] = v;
    __syncthreads();
#pragma unroll
    for (int off = 1; off < 64; off <<= 1) {
        int t = (tid >= off) ? sh[tid - off] : 0;
        __syncthreads();
        sh[tid] += t;
        __syncthreads();
    }
    if (tid < SCAN_BLOCKS) part[tid] = sh[tid] - v;
    if (tid == 63) part[SCAN_BLOCKS] = sh[63];
}

__global__ void scan_add(int* __restrict__ rowptr, const int* __restrict__ part,
                         int* __restrict__ posn) {
    int i = blockIdx.x * blockDim.x + threadIdx.x;
    if (i < N_NODES) {
        int r = rowptr[i] + part[i >> 10];
        rowptr[i] = r;
        posn[i] = r;
    }
    if (i == 0) rowptr[N_NODES] = part[SCAN_BLOCKS];
}

__global__ void scatter_kernel(const int* __restrict__ src, const int* __restrict__ dst,
                               int* __restrict__ posn, int* __restrict__ esrc) {
    int e = blockIdx.x * blockDim.x + threadIdx.x;
    if (e < N_EDGES) {
        int idx = atomicAdd(&posn[dst[e]], 1);
        esrc[idx] = src[e];
    }
}

// ---------------- fused conv1: embed + 3-wide gather + linear + split -------------
__global__ void __launch_bounds__(256)
conv1_fused(const int* __restrict__ x, const float* __restrict__ emb,
            const int* __restrict__ rowptr, const int* __restrict__ esrc,
            const float* __restrict__ w_rel, const float* __restrict__ w_root,
            const float* __restrict__ b,
            float* __restrict__ h1, __nv_bfloat16* __restrict__ h1h,
            __nv_bfloat16* __restrict__ h1l) {
    __shared__ float swr[192], swo[192], sb[64];
    int tid = threadIdx.x;
    if (tid < 192) { swr[tid] = w_rel[tid]; swo[tid] = w_root[tid]; }
    if (tid < 64) sb[tid] = b[tid];
    __syncthreads();
    int node = blockIdx.x * 8 + (tid >> 5);
    int lane = tid & 31;
    if (node >= N_NODES) return;
    int bg = rowptr[node], en = rowptr[node + 1];
    float a0 = 0.f, a1 = 0.f, a2 = 0.f;
    for (int j = bg + lane; j < en; j += 32) {
        int s = esrc[j];
        int lab = x[s];
        a0 += emb[lab * 3 + 0];
        a1 += emb[lab * 3 + 1];
        a2 += emb[lab * 3 + 2];
    }
#pragma unroll
    for (int o = 16; o; o >>= 1) {
        a0 += __shfl_xor_sync(0xffffffff, a0, o);
        a1 += __shfl_xor_sync(0xffffffff, a1, o);
        a2 += __shfl_xor_sync(0xffffffff, a2, o);
    }
    int labn = x[node];
    float x0 = emb[labn * 3 + 0], x1 = emb[labn * 3 + 1], x2 = emb[labn * 3 + 2];
    int c = lane * 2;
    float v0 = sb[c]   + a0*swr[c]   + a1*swr[64+c]   + a2*swr[128+c]
                       + x0*swo[c]   + x1*swo[64+c]   + x2*swo[128+c];
    float v1 = sb[c+1] + a0*swr[c+1] + a1*swr[64+c+1] + a2*swr[128+c+1]
                       + x0*swo[c+1] + x1*swo[64+c+1] + x2*swo[128+c+1];
    v0 = lrelu(v0); v1 = lrelu(v1);
    *reinterpret_cast<float2*>(h1 + (size_t)node * 64 + c) = make_float2(v0, v1);
    float h0f = bf_round(v0), h1f = bf_round(v1);
    reinterpret_cast<uint32_t*>(h1h)[node * 32 + lane] = pack_bf16(h0f, h1f);
    reinterpret_cast<uint32_t*>(h1l)[node * 32 + lane] = pack_bf16(v0 - h0f, v1 - h1f);
}

// ---------------- CSR gather, C=64 -> hi/lo bf16 only -----------------------------
__global__ void gather_h16(const float* __restrict__ xin,
                           __nv_bfloat16* __restrict__ oh, __nv_bfloat16* __restrict__ ol,
                           const int* __restrict__ rowptr, const int* __restrict__ esrc) {
    int i = blockIdx.x * blockDim.x + threadIdx.x;
    if (i >= N_NODES * 16) return;
    int node = i >> 4, c = i & 15;
    int bg = rowptr[node], en = rowptr[node + 1];
    float4 acc = make_float4(0.f, 0.f, 0.f, 0.f);
    for (int j = bg; j < en; j++) {
        int s = esrc[j];
        float4 v = reinterpret_cast<const float4*>(xin)[(size_t)s * 16 + c];
        acc.x += v.x; acc.y += v.y; acc.z += v.z; acc.w += v.w;
    }
    float hx = bf_round(acc.x), hy = bf_round(acc.y), hz = bf_round(acc.z), hw = bf_round(acc.w);
    uint32_t* oh32 = reinterpret_cast<uint32_t*>(oh);
    uint32_t* ol32 = reinterpret_cast<uint32_t*>(ol);
    oh32[node * 32 + c * 2]     = pack_bf16(hx, hy);
    oh32[node * 32 + c * 2 + 1] = pack_bf16(hz, hw);
    ol32[node * 32 + c * 2]     = pack_bf16(acc.x - hx, acc.y - hy);
    ol32[node * 32 + c * 2 + 1] = pack_bf16(acc.z - hz, acc.w - hw);
}

// ---------------- enc finish (2 warps per node, half each) ------------------------
// bufE [N][512]: rel cols 0-255, root cols 256-511.
__global__ void __launch_bounds__(256)
gather_enc_fin(const float* __restrict__ bufE, const float* __restrict__ be,
               float* __restrict__ lat, __nv_bfloat16* __restrict__ lath,
               __nv_bfloat16* __restrict__ latl,
               const int* __restrict__ rowptr, const int* __restrict__ esrc,
               const int* __restrict__ batch, float* __restrict__ pooled) {
    int gw = (blockIdx.x * blockDim.x + threadIdx.x) >> 5;   // global warp
    int node = gw >> 1;
    int half = gw & 1;                                       // 0: cols 0-31, 1: cols 32-63
    int lane = threadIdx.x & 31;
    if (node >= N_NODES) return;
    int col = half * 32 + lane;                              // float4 column 0..63
    int bg = rowptr[node], en = rowptr[node + 1];
    float4 acc = make_float4(0.f, 0.f, 0.f, 0.f);
    int j = bg;
#pragma unroll 2
    for (; j < en; j++) {
        int s = esrc[j];                                     // broadcast load
        float4 v = reinterpret_cast<const float4*>(bufE)[(size_t)s * 128 + col];
        acc.x += v.x; acc.y += v.y; acc.z += v.z; acc.w += v.w;
    }
    float4 rt = reinterpret_cast<const float4*>(bufE)[(size_t)node * 128 + 64 + col];
    float4 b4 = reinterpret_cast<const float4*>(be)[col];
    float4 o;
    o.x = lrelu(acc.x + rt.x + b4.x);
    o.y = lrelu(acc.y + rt.y + b4.y);
    o.z = lrelu(acc.z + rt.z + b4.z);
    o.w = lrelu(acc.w + rt.w + b4.w);
    reinterpret_cast<float4*>(lat)[(size_t)node * 64 + col] = o;
    uint32_t* oh32 = reinterpret_cast<uint32_t*>(lath) + (size_t)node * 128;
    uint32_t* ol32 = reinterpret_cast<uint32_t*>(latl) + (size_t)node * 128;
    float h0 = bf_round(o.x), h1 = bf_round(o.y), h2 = bf_round(o.z), h3 = bf_round(o.w);
    oh32[col * 2]     = pack_bf16(h0, h1);
    oh32[col * 2 + 1] = pack_bf16(h2, h3);
    ol32[col * 2]     = pack_bf16(o.x - h0, o.y - h1);
    ol32[col * 2 + 1] = pack_bf16(o.z - h2, o.w - h3);
    int g = batch[node];
    red_add_v4(reinterpret_cast<float4*>(pooled) + (size_t)g * 64 + col, o);
}

// ---------------- CSR gather (2 warps per node), C=256 -> hi/lo -------------------
__global__ void __launch_bounds__(256)
gather_c256(const float* __restrict__ xin,
            __nv_bfloat16* __restrict__ oh, __nv_bfloat16* __restrict__ ol,
            const int* __restrict__ rowptr, const int* __restrict__ esrc) {
    int gw = (blockIdx.x * blockDim.x + threadIdx.x) >> 5;
    int node = gw >> 1;
    int half = gw & 1;
    int lane = threadIdx.x & 31;
    if (node >= N_NODES) return;
    int col = half * 32 + lane;
    int bg = rowptr[node], en = rowptr[node + 1];
    float4 acc = make_float4(0.f, 0.f, 0.f, 0.f);
    int j = bg;
#pragma unroll 2
    for (; j < en; j++) {
        int s = esrc[j];
        float4 v = reinterpret_cast<const float4*>(xin)[(size_t)s * 64 + col];
        acc.x += v.x; acc.y += v.y; acc.z += v.z; acc.w += v.w;
    }
    uint32_t* oh32 = reinterpret_cast<uint32_t*>(oh) + (size_t)node * 128;
    uint32_t* ol32 = reinterpret_cast<uint32_t*>(ol) + (size_t)node * 128;
    float h0 = bf_round(acc.x), h1 = bf_round(acc.y), h2 = bf_round(acc.z), h3 = bf_round(acc.w);
    oh32[col * 2]     = pack_bf16(h0, h1);
    oh32[col * 2 + 1] = pack_bf16(h2, h3);
    ol32[col * 2]     = pack_bf16(acc.x - h0, acc.y - h1);
    ol32[col * 2 + 1] = pack_bf16(acc.z - h2, acc.w - h3);
}

// ---------------- transpose + hi/lo split (paired) --------------------------------
__global__ void transpose_split2(const float* __restrict__ W1, __nv_bfloat16* __restrict__ oh1,
                                 __nv_bfloat16* __restrict__ ol1,
                                 const float* __restrict__ W2, __nv_bfloat16* __restrict__ oh2,
                                 __nv_bfloat16* __restrict__ ol2, int K, int N) {
    const float* W = blockIdx.z ? W2 : W1;
    __nv_bfloat16* oh = blockIdx.z ? oh2 : oh1;
    __nv_bfloat16* ol = blockIdx.z ? ol2 : ol1;
    __shared__ float tile[32][33];
    int n0 = blockIdx.x * 32, k0 = blockIdx.y * 32;
    int tx = threadIdx.x, ty = threadIdx.y;
#pragma unroll
    for (int j = 0; j < 32; j += 8)
        tile[ty + j][tx] = W[(size_t)(k0 + ty + j) * N + n0 + tx];
    __syncthreads();
#pragma unroll
    for (int j = 0; j < 32; j += 8) {
        float v = tile[tx][ty + j];
        float h = bf_round(v);
        size_t o = (size_t)(n0 + ty + j) * K + k0 + tx;
        oh[o] = __float2bfloat16(h);
        ol[o] = __float2bfloat16(v - h);
    }
}

// ---------------- 3-stage cp.async pre-split bf16 GEMM (XOR-swizzled) -------------
#define OFF_AL   8192            // 128 rows * 64 B
#define OFF_BH   16384
#define OFF_BL   24576
#define STAGE_B  32768
#define GEMM_SMEM (3 * STAGE_B)  // 98304; 2 CTAs/SM = 196608

__global__ void __launch_bounds__(512, 2)
gemm_split(const __nv_bfloat16* __restrict__ A1h, const __nv_bfloat16* __restrict__ A1l, int K1,
           const __nv_bfloat16* __restrict__ A2h, const __nv_bfloat16* __restrict__ A2l, int K2,
           const __nv_bfloat16* __restrict__ W1h, const __nv_bfloat16* __restrict__ W1l,
           const __nv_bfloat16* __restrict__ W2h, const __nv_bfloat16* __restrict__ W2l,
           const float* __restrict__ add, const float* __restrict__ bias,
           float* __restrict__ C, __nv_bfloat16* __restrict__ Ch,
           __nv_bfloat16* __restrict__ Cl, int M, int N, int leaky) {
    extern __shared__ __align__(16) char smc[];
    int tid = threadIdx.x;
    int lane = tid & 31, wid = tid >> 5;
    int wm = (wid & 3) * 32;
    int wn = (wid >> 2) * 32;
    int brow = blockIdx.y * 128;
    int bcol = blockIdx.x * 128;
    uint32_t sbase = (uint32_t)__cvta_generic_to_shared(smc);

    float acc[2][4][4];
#pragma unroll
    for (int mt = 0; mt < 2; mt++)
#pragma unroll
        for (int nt = 0; nt < 4; nt++)
#pragma unroll
            for (int r = 0; r < 4; r++) acc[mt][nt][r] = 0.f;

    int T1 = A1h ? (K1 / 32) : 0;
    int T2 = A2h ? (K2 / 32) : 0;
    int T = T1 + T2;

    int srow = tid >> 2;
    int sc   = tid & 3;
    uint32_t sphys = srow * 64 + ((sc ^ ((srow >> 1) & 3)) << 4);

    int lr = lane & 7;
    uint32_t a_row[2]; int qa[2];
#pragma unroll
    for (int mt = 0; mt < 2; mt++) {
        int row = wm + mt * 16 + ((lane >> 3) & 1) * 8 + lr;
        a_row[mt] = row * 64;
        qa[mt] = (row >> 1) & 3;
    }
    uint32_t b_row[2]; int qb[2];
#pragma unroll
    for (int p = 0; p < 2; p++) {
        int n = wn + p * 16 + (lane >> 4) * 8 + lr;
        b_row[p] = n * 64;
        qb[p] = (n >> 1) & 3;
    }
    int ca = lane >> 4;
    int cb = (lane >> 3) & 1;

    auto issue = [&](int t, int stage) {
        const __nv_bfloat16 *Ah, *Al, *Wh, *Wl; int K, k0;
        if (t < T1) { Ah = A1h; Al = A1l; Wh = W1h; Wl = W1l; K = K1; k0 = t * 32; }
        else        { Ah = A2h; Al = A2l; Wh = W2h; Wl = W2l; K = K2; k0 = (t - T1) * 32; }
        uint32_t sb = sbase + stage * STAGE_B;
        size_t go = (size_t)(brow + srow) * K + k0 + sc * 8;
        cp16(sb + sphys, Ah + go);
        cp16(sb + OFF_AL + sphys, Al + go);
        size_t gb = (size_t)(bcol + srow) * K + k0 + sc * 8;
        cp16(sb + OFF_BH + sphys, Wh + gb);
        cp16(sb + OFF_BL + sphys, Wl + gb);
        cp_commit();
    };

    auto compute = [&](int stage) {
        uint32_t sb = sbase + stage * STAGE_B;
#pragma unroll
        for (int ks = 0; ks < 2; ks++) {
            uint32_t aH[2][4], aL[2][4], bH[4][2], bL[4][2];
#pragma unroll
            for (int mt = 0; mt < 2; mt++) {
                uint32_t off = a_row[mt] + ((((ks << 1) | ca) ^ qa[mt]) << 4);
                ldsm4(aH[mt], sb + off);
                ldsm4(aL[mt], sb + OFF_AL + off);
            }
#pragma unroll
            for (int p = 0; p < 2; p++) {
                uint32_t off = b_row[p] + ((((ks << 1) | cb) ^ qb[p]) << 4);
                ldsm4(&bH[p * 2][0], sb + OFF_BH + off);
                ldsm4(&bL[p * 2][0], sb + OFF_BL + off);
            }
#pragma unroll
            for (int mt = 0; mt < 2; mt++)
#pragma unroll
                for (int nt = 0; nt < 4; nt++) {
                    mma_bf16(acc[mt][nt], aH[mt], bH[nt]);
                    mma_bf16(acc[mt][nt], aH[mt], bL[nt]);
                    mma_bf16(acc[mt][nt], aL[mt], bH[nt]);
                }
        }
    };

    // ---- 3-stage ring, 2 chunks in flight, one sync per chunk ----
#pragma unroll
    for (int i = 0; i < 2; i++) {
        if (i < T) issue(i, i);
        else cp_commit();
    }
#pragma unroll 1
    for (int t = 0; t < T; t++) {
        cp_wait<1>();
        __syncthreads();
        if (t + 2 < T) issue(t + 2, (t + 2) % 3);
        else cp_commit();
        compute(t % 3);
    }

    // ---- epilogue ----
#pragma unroll
    for (int mt = 0; mt < 2; mt++) {
#pragma unroll
        for (int nt = 0; nt < 4; nt++) {
            int r0 = brow + wm + mt * 16 + (lane >> 2);
            int c  = bcol + wn + nt * 8 + (lane & 3) * 2;
#pragma unroll
            for (int half = 0; half < 2; half++) {
                int row = r0 + half * 8;
                if (row >= M) continue;
                float v0 = acc[mt][nt][half * 2 + 0];
                float v1 = acc[mt][nt][half * 2 + 1];
                if (add) {
                    const float2 a2 = *reinterpret_cast<const float2*>(add + (size_t)row * N + c);
                    v0 += a2.x; v1 += a2.y;
                }
                if (bias) {
                    const float2 b2 = *reinterpret_cast<const float2*>(bias + c);
                    v0 += b2.x; v1 += b2.y;
                }
                if (leaky) { v0 = lrelu(v0); v1 = lrelu(v1); }
                *reinterpret_cast<float2*>(C + (size_t)row * N + c) = make_float2(v0, v1);
                if (Ch) {
                    float h0 = bf_round(v0), h1f = bf_round(v1);
                    *reinterpret_cast<uint32_t*>(Ch + (size_t)row * N + c) = pack_bf16(h0, h1f);
                    *reinterpret_cast<uint32_t*>(Cl + (size_t)row * N + c) = pack_bf16(v0 - h0, v1 - h1f);
                }
            }
        }
    }
}

// ---------------- logits ----------------------------------------------------------
__global__ void logits_kernel(const float* __restrict__ pooled, const float* __restrict__ counts,
                              const float* __restrict__ w_lin, const float* __restrict__ b_lin,
                              float* __restrict__ out) {
    int g = blockIdx.x;
    int o = threadIdx.x;
    if (o >= OUT_CLS) return;
    float inv = 1.0f / fmaxf(counts[g], 1.0f);
    float s = 0.f;
    const float* pr = pooled + g * 256;
    for (int k = 0; k < 256; k++) s += pr[k] * w_lin[k * OUT_CLS + o];
    out[g * OUT_CLS + o] = s * inv + b_lin[o];
}

// ---------------- host launch -----------------------------------------------------
extern "C" void kernel_launch(void* const* d_in, const int* in_sizes, int n_in,
                              void* d_out, int out_size) {
    const int*   x       = (const int*)d_in[0];
    const int*   ei      = (const int*)d_in[1];
    const int*   batch   = (const int*)d_in[2];
    const float* emb     = (const float*)d_in[3];
    const float* w1_rel  = (const float*)d_in[4];
    const float* w1_root = (const float*)d_in[5];
    const float* b1      = (const float*)d_in[6];
    const float* w2_rel  = (const float*)d_in[7];
    const float* w2_root = (const float*)d_in[8];
    const float* b2      = (const float*)d_in[9];
    const float* we_rel  = (const float*)d_in[10];
    const float* we_root = (const float*)d_in[11];
    const float* be      = (const float*)d_in[12];
    const float* wd_rel  = (const float*)d_in[13];
    const float* wd_root = (const float*)d_in[14];
    const float* bd      = (const float*)d_in[15];
    const float* w_lin   = (const float*)d_in[16];
    const float* b_lin   = (const float*)d_in[17];

    const int* src = ei;
    const int* dst = ei + N_EDGES;

    float* out    = (float*)d_out;
    float* logits = out;
    float* recon  = out + OFF_RECON;
    float* orig   = out + OFF_ORIG;

    float *h1, *bufE, *lat, *pool, *cnt;
    int *deg, *rowptr, *posn, *esrc, *part;
    cudaGetSymbolAddress((void**)&h1,    g_h1);
    cudaGetSymbolAddress((void**)&bufE,  g_enc);
    cudaGetSymbolAddress((void**)&lat,   g_lat);
    cudaGetSymbolAddress((void**)&pool,  g_pool);
    cudaGetSymbolAddress((void**)&cnt,   g_cnt);
    cudaGetSymbolAddress((void**)&deg,   g_deg);
    cudaGetSymbolAddress((void**)&rowptr,g_rowptr);
    cudaGetSymbolAddress((void**)&posn,  g_posn);
    cudaGetSymbolAddress((void**)&esrc,  g_esrc);
    cudaGetSymbolAddress((void**)&part,  g_part);

    __nv_bfloat16 *h1h,*h1l,*a1h,*a1l,*oh,*ol,*lath,*latl,*aggh,*aggl;
    __nv_bfloat16 *w2rh,*w2rl,*w2oh,*w2ol,*wcath,*wcatl,*wdrh,*wdrl,*wdoh,*wdol;
    cudaGetSymbolAddress((void**)&h1h, g_h1h);   cudaGetSymbolAddress((void**)&h1l, g_h1l);
    cudaGetSymbolAddress((void**)&a1h, g_a1h);   cudaGetSymbolAddress((void**)&a1l, g_a1l);
    cudaGetSymbolAddress((void**)&oh,  g_oh);    cudaGetSymbolAddress((void**)&ol,  g_ol);
    cudaGetSymbolAddress((void**)&lath,g_lath);  cudaGetSymbolAddress((void**)&latl,g_latl);
    cudaGetSymbolAddress((void**)&aggh,g_aggh);  cudaGetSymbolAddress((void**)&aggl,g_aggl);
    cudaGetSymbolAddress((void**)&w2rh,g_w2r_h); cudaGetSymbolAddress((void**)&w2rl,g_w2r_l);
    cudaGetSymbolAddress((void**)&w2oh,g_w2o_h); cudaGetSymbolAddress((void**)&w2ol,g_w2o_l);
    cudaGetSymbolAddress((void**)&wcath,g_wcat_h); cudaGetSymbolAddress((void**)&wcatl,g_wcat_l);
    cudaGetSymbolAddress((void**)&wdrh,g_wdr_h); cudaGetSymbolAddress((void**)&wdrl,g_wdr_l);
    cudaGetSymbolAddress((void**)&wdoh,g_wdo_h); cudaGetSymbolAddress((void**)&wdol,g_wdo_l);

    cudaFuncSetAttribute(gemm_split, cudaFuncAttributeMaxDynamicSharedMemorySize, GEMM_SMEM);

    // CSR build
    zero_misc<<<256, 256>>>(deg, pool, cnt);
    hist_kernel<<<(N_EDGES + 255) / 256, 256>>>(dst, deg, batch, cnt);
    scan_local<<<SCAN_BLOCKS, 1024>>>(deg, rowptr, part);
    scan_partials<<<1, 64>>>(part);
    scan_add<<<(N_NODES + 255) / 256, 256>>>(rowptr, part, posn);
    scatter_kernel<<<(N_EDGES + 255) / 256, 256>>>(src, dst, posn, esrc);

    // fused conv1
    conv1_fused<<<(N_NODES + 7) / 8, 256>>>(x, emb, rowptr, esrc,
                                            w1_rel, w1_root, b1, h1, h1h, h1l);

    // 64-wide gather (h1 -> aggr hi/lo)
    gather_h16<<<(N_NODES * 16 + 255) / 256, 256>>>(h1, a1h, a1l, rowptr, esrc);

    // w2 transposes (paired)
    {
        dim3 b(32, 8);
        transpose_split2<<<dim3(1024/32, 64/32, 2), b>>>(w2_rel, w2rh, w2rl,
                                                         w2_root, w2oh, w2ol, 64, 1024);
    }
    // conv2 GEMM -> orig (+hi/lo)
    {
        dim3 grid(1024 / 128, (N_NODES + 127) / 128);
        gemm_split<<<grid, 512, GEMM_SMEM>>>(a1h, a1l, 64, h1h, h1l, 64,
                                             w2rh, w2rl, w2oh, w2ol,
                                             nullptr, b2, orig, oh, ol, N_NODES, 1024, 1);
    }

    // we transposes (paired) -> concatenated [512][1024]
    {
        dim3 b(32, 8);
        transpose_split2<<<dim3(256/32, 1024/32, 2), b>>>(we_rel, wcath, wcatl,
                                                          we_root, wcath + 256 * 1024,
                                                          wcatl + 256 * 1024, 1024, 256);
    }
    // fused enc GEMM (N=512): bufE = [orig@we_rel | orig@we_root]
    {
        dim3 grid(512 / 128, (N_NODES + 127) / 128);
        gemm_split<<<grid, 512, GEMM_SMEM>>>(oh, ol, 1024, nullptr, nullptr, 0,
                                             wcath, wcatl, nullptr, nullptr,
                                             nullptr, nullptr, bufE, nullptr, nullptr,
                                             N_NODES, 512, 0);
    }
    // enc finish (2 warps/node): gather rel + root + bias + leaky -> lat (+hi/lo) + pool
    gather_enc_fin<<<(N_NODES * 64 + 255) / 256, 256>>>(bufE, be, lat, lath, latl,
                                                        rowptr, esrc, batch, pool);

    // 256-wide gather (2 warps/node) lat -> agg hi/lo
    gather_c256<<<(N_NODES * 64 + 255) / 256, 256>>>(lat, aggh, aggl, rowptr, esrc);

    // logits
    logits_kernel<<<N_GRAPHS, 32>>>(pool, cnt, w_lin, b_lin, logits);

    // wd transposes (paired)
    {
        dim3 b(32, 8);
        transpose_split2<<<dim3(1024/32, 256/32, 2), b>>>(wd_rel, wdrh, wdrl,
                                                          wd_root, wdoh, wdol, 256, 1024);
    }
    // dec GEMM -> recon
    {
        dim3 grid(1024 / 128, (N_NODES + 127) / 128);
        gemm_split<<<grid, 512, GEMM_SMEM>>>(aggh, aggl, 256, lath, latl, 256,
                                             wdrh, wdrl, wdoh, wdol,
                                             nullptr, bd, recon, nullptr, nullptr,
                                             N_NODES, 1024, 1);
    }
}

// round 15
// speedup vs baseline: 1.0120x; 1.0120x over previous
#include <cuda_runtime.h>
#include <cuda_bf16.h>
#include <cstdint>

#define N_NODES 50000
#define M_PAD   50048
#define N_EDGES 800000
#define N_GRAPHS 256
#define OUT_CLS 7
#define NEG_SLOPE 0.01f

// Output layout: logits [256*7] | reconstructed [N*1024] | original [N*1024]
#define OFF_RECON (N_GRAPHS * OUT_CLS)
#define OFF_ORIG  (OFF_RECON + N_NODES * 1024)

// ---------------- fp32 scratch ----------------------------------------------------
__device__ float g_h1   [N_NODES * 64];
__device__ float g_enc  [N_NODES * 512];   // fused enc GEMM output: [rel(256) | root(256)]
__device__ float g_lat  [N_NODES * 256];
__device__ float g_pool [N_GRAPHS * 256];
__device__ float g_cnt  [N_GRAPHS];

// ---------------- CSR scratch -----------------------------------------------------
#define SCAN_BLOCKS ((N_NODES + 1023) / 1024)
__device__ int g_deg   [N_NODES];
__device__ int g_rowptr[N_NODES + 1];
__device__ int g_posn  [N_NODES];
__device__ int g_esrc  [N_EDGES];
__device__ int g_part  [SCAN_BLOCKS + 1];

// ---------------- pre-split bf16 scratch (hi/lo), padded rows ---------------------
__device__ __nv_bfloat16 g_h1h [M_PAD * 64];
__device__ __nv_bfloat16 g_h1l [M_PAD * 64];
__device__ __nv_bfloat16 g_a1h [M_PAD * 64];
__device__ __nv_bfloat16 g_a1l [M_PAD * 64];
__device__ __nv_bfloat16 g_oh  [M_PAD * 1024];
__device__ __nv_bfloat16 g_ol  [M_PAD * 1024];
__device__ __nv_bfloat16 g_lath[M_PAD * 256];
__device__ __nv_bfloat16 g_latl[M_PAD * 256];
__device__ __nv_bfloat16 g_aggh[M_PAD * 256];
__device__ __nv_bfloat16 g_aggl[M_PAD * 256];
// transposed weights [N][K] hi/lo
__device__ __nv_bfloat16 g_w2r_h[1024 * 64],  g_w2r_l[1024 * 64];
__device__ __nv_bfloat16 g_w2o_h[1024 * 64],  g_w2o_l[1024 * 64];
__device__ __nv_bfloat16 g_wcat_h[512 * 1024], g_wcat_l[512 * 1024];  // [we_rel ; we_root]
__device__ __nv_bfloat16 g_wdr_h[1024 * 256], g_wdr_l[1024 * 256];
__device__ __nv_bfloat16 g_wdo_h[1024 * 256], g_wdo_l[1024 * 256];

// ---------------- helpers ---------------------------------------------------------
__device__ __forceinline__ void red_add_v4(float4* addr, float4 v) {
    asm volatile("red.global.add.v4.f32 [%0], {%1, %2, %3, %4};"
                 :: "l"(addr), "f"(v.x), "f"(v.y), "f"(v.z), "f"(v.w) : "memory");
}
__device__ __forceinline__ float lrelu(float v) { return v >= 0.f ? v : NEG_SLOPE * v; }

__device__ __forceinline__ uint32_t pack_bf16(float x, float y) {
    __nv_bfloat162 t = __floats2bfloat162_rn(x, y);
    return *reinterpret_cast<uint32_t*>(&t);
}
__device__ __forceinline__ float bf_round(float v) {
    return __bfloat162float(__float2bfloat16(v));
}

__device__ __forceinline__ void mma_bf16(float* d, const uint32_t* a, const uint32_t* b) {
    asm volatile(
        "mma.sync.aligned.m16n8k16.row.col.f32.bf16.bf16.f32 "
        "{%0,%1,%2,%3}, {%4,%5,%6,%7}, {%8,%9}, {%0,%1,%2,%3};"
        : "+f"(d[0]), "+f"(d[1]), "+f"(d[2]), "+f"(d[3])
        : "r"(a[0]), "r"(a[1]), "r"(a[2]), "r"(a[3]), "r"(b[0]), "r"(b[1]));
}

__device__ __forceinline__ void ldsm4(uint32_t* r, uint32_t addr) {
    asm volatile("ldmatrix.sync.aligned.m8n8.x4.shared.b16 {%0,%1,%2,%3}, [%4];"
                 : "=r"(r[0]), "=r"(r[1]), "=r"(r[2]), "=r"(r[3]) : "r"(addr));
}

__device__ __forceinline__ void cp16(uint32_t dst, const void* src) {
    asm volatile("cp.async.cg.shared.global [%0], [%1], 16;" :: "r"(dst), "l"(src));
}
__device__ __forceinline__ void cp_commit() { asm volatile("cp.async.commit_group;"); }
template <int Np> __device__ __forceinline__ void cp_wait() {
    asm volatile("cp.async.wait_group %0;" :: "n"(Np));
}

// ---------------- CSR build -------------------------------------------------------
__global__ void zero_misc(int* deg, float* pool, float* cnt) {
    int i = blockIdx.x * blockDim.x + threadIdx.x;
    if (i < N_NODES) deg[i] = 0;
    if (i < N_GRAPHS * 256) pool[i] = 0.f;
    if (i < N_GRAPHS) cnt[i] = 0.f;
}

__global__ void hist_kernel(const int* __restrict__ dst, int* __restrict__ deg,
                            const int* __restrict__ batch, float* __restrict__ counts) {
    int e = blockIdx.x * blockDim.x + threadIdx.x;
    if (e < N_EDGES) atomicAdd(&deg[dst[e]], 1);
    if (e < N_NODES) atomicAdd(&counts[batch[e]], 1.0f);
}

__global__ void scan_local(const int* __restrict__ deg, int* __restrict__ rowptr,
                           int* __restrict__ part) {
    __shared__ int sh[1024];
    int tid = threadIdx.x;
    int i = blockIdx.x * 1024 + tid;
    int v = (i < N_NODES) ? deg[i] : 0;
    sh[tid] = v;
    __syncthreads();
#pragma unroll
    for (int off = 1; off < 1024; off <<= 1) {
        int t = (tid >= off) ? sh[tid - off] : 0;
        __syncthreads();
        sh[tid] += t;
        __syncthreads();
    }
    if (i < N_NODES) rowptr[i] = sh[tid] - v;
    if (tid == 1023) part[blockIdx.x] = sh[1023];
}

__global__ void scan_partials(int* __restrict__ part) {
    __shared__ int sh[64];
    int tid = threadIdx.x;
    int v = (tid < SCAN_BLOCKS) ? part[tid] : 0;
    sh[tid] = v;
    __syncthreads();
#pragma unroll
    for (int off = 1; off < 64; off <<= 1) {
        int t = (tid >= off) ? sh[tid - off] : 0;
        __syncthreads();
        sh[tid] += t;
        __syncthreads();
    }
    if (tid < SCAN_BLOCKS) part[tid] = sh[tid] - v;
    if (tid == 63) part[SCAN_BLOCKS] = sh[63];
}

__global__ void scan_add(int* __restrict__ rowptr, const int* __restrict__ part,
                         int* __restrict__ posn) {
    int i = blockIdx.x * blockDim.x + threadIdx.x;
    if (i < N_NODES) {
        int r = rowptr[i] + part[i >> 10];
        rowptr[i] = r;
        posn[i] = r;
    }
    if (i == 0) rowptr[N_NODES] = part[SCAN_BLOCKS];
}

__global__ void scatter_kernel(const int* __restrict__ src, const int* __restrict__ dst,
                               int* __restrict__ posn, int* __restrict__ esrc) {
    int e = blockIdx.x * blockDim.x + threadIdx.x;
    if (e < N_EDGES) {
        int idx = atomicAdd(&posn[dst[e]], 1);
        esrc[idx] = src[e];
    }
}

// ---------------- fused conv1: embed + 3-wide gather + linear + split -------------
__global__ void __launch_bounds__(256)
conv1_fused(const int* __restrict__ x, const float* __restrict__ emb,
            const int* __restrict__ rowptr, const int* __restrict__ esrc,
            const float* __restrict__ w_rel, const float* __restrict__ w_root,
            const float* __restrict__ b,
            float* __restrict__ h1, __nv_bfloat16* __restrict__ h1h,
            __nv_bfloat16* __restrict__ h1l) {
    __shared__ float swr[192], swo[192], sb[64];
    int tid = threadIdx.x;
    if (tid < 192) { swr[tid] = w_rel[tid]; swo[tid] = w_root[tid]; }
    if (tid < 64) sb[tid] = b[tid];
    __syncthreads();
    int node = blockIdx.x * 8 + (tid >> 5);
    int lane = tid & 31;
    if (node >= N_NODES) return;
    int bg = rowptr[node], en = rowptr[node + 1];
    float a0 = 0.f, a1 = 0.f, a2 = 0.f;
    for (int j = bg + lane; j < en; j += 32) {
        int s = esrc[j];
        int lab = x[s];
        a0 += emb[lab * 3 + 0];
        a1 += emb[lab * 3 + 1];
        a2 += emb[lab * 3 + 2];
    }
#pragma unroll
    for (int o = 16; o; o >>= 1) {
        a0 += __shfl_xor_sync(0xffffffff, a0, o);
        a1 += __shfl_xor_sync(0xffffffff, a1, o);
        a2 += __shfl_xor_sync(0xffffffff, a2, o);
    }
    int labn = x[node];
    float x0 = emb[labn * 3 + 0], x1 = emb[labn * 3 + 1], x2 = emb[labn * 3 + 2];
    int c = lane * 2;
    float v0 = sb[c]   + a0*swr[c]   + a1*swr[64+c]   + a2*swr[128+c]
                       + x0*swo[c]   + x1*swo[64+c]   + x2*swo[128+c];
    float v1 = sb[c+1] + a0*swr[c+1] + a1*swr[64+c+1] + a2*swr[128+c+1]
                       + x0*swo[c+1] + x1*swo[64+c+1] + x2*swo[128+c+1];
    v0 = lrelu(v0); v1 = lrelu(v1);
    *reinterpret_cast<float2*>(h1 + (size_t)node * 64 + c) = make_float2(v0, v1);
    float h0f = bf_round(v0), h1f = bf_round(v1);
    reinterpret_cast<uint32_t*>(h1h)[node * 32 + lane] = pack_bf16(h0f, h1f);
    reinterpret_cast<uint32_t*>(h1l)[node * 32 + lane] = pack_bf16(v0 - h0f, v1 - h1f);
}

// ---------------- CSR gather, C=64 -> hi/lo bf16 only -----------------------------
__global__ void gather_h16(const float* __restrict__ xin,
                           __nv_bfloat16* __restrict__ oh, __nv_bfloat16* __restrict__ ol,
                           const int* __restrict__ rowptr, const int* __restrict__ esrc) {
    int i = blockIdx.x * blockDim.x + threadIdx.x;
    if (i >= N_NODES * 16) return;
    int node = i >> 4, c = i & 15;
    int bg = rowptr[node], en = rowptr[node + 1];
    float4 acc = make_float4(0.f, 0.f, 0.f, 0.f);
    for (int j = bg; j < en; j++) {
        int s = esrc[j];
        float4 v = reinterpret_cast<const float4*>(xin)[(size_t)s * 16 + c];
        acc.x += v.x; acc.y += v.y; acc.z += v.z; acc.w += v.w;
    }
    float hx = bf_round(acc.x), hy = bf_round(acc.y), hz = bf_round(acc.z), hw = bf_round(acc.w);
    uint32_t* oh32 = reinterpret_cast<uint32_t*>(oh);
    uint32_t* ol32 = reinterpret_cast<uint32_t*>(ol);
    oh32[node * 32 + c * 2]     = pack_bf16(hx, hy);
    oh32[node * 32 + c * 2 + 1] = pack_bf16(hz, hw);
    ol32[node * 32 + c * 2]     = pack_bf16(acc.x - hx, acc.y - hy);
    ol32[node * 32 + c * 2 + 1] = pack_bf16(acc.z - hz, acc.w - hw);
}

// ---------------- enc finish (warp per node) --------------------------------------
__global__ void __launch_bounds__(256)
gather_enc_fin(const float* __restrict__ bufE, const float* __restrict__ be,
               float* __restrict__ lat, __nv_bfloat16* __restrict__ lath,
               __nv_bfloat16* __restrict__ latl,
               const int* __restrict__ rowptr, const int* __restrict__ esrc,
               const int* __restrict__ batch, float* __restrict__ pooled) {
    int node = (blockIdx.x * blockDim.x + threadIdx.x) >> 5;
    int lane = threadIdx.x & 31;
    if (node >= N_NODES) return;
    int bg = rowptr[node], en = rowptr[node + 1];
    float4 acc0 = make_float4(0.f, 0.f, 0.f, 0.f);
    float4 acc1 = make_float4(0.f, 0.f, 0.f, 0.f);
#pragma unroll 2
    for (int j = bg; j < en; j++) {
        int s = esrc[j];
        const float4* row = reinterpret_cast<const float4*>(bufE) + (size_t)s * 128;
        float4 v0 = row[lane];
        float4 v1 = row[lane + 32];
        acc0.x += v0.x; acc0.y += v0.y; acc0.z += v0.z; acc0.w += v0.w;
        acc1.x += v1.x; acc1.y += v1.y; acc1.z += v1.z; acc1.w += v1.w;
    }
    const float4* nrow = reinterpret_cast<const float4*>(bufE) + (size_t)node * 128 + 64;
    float4 rt0 = nrow[lane];
    float4 rt1 = nrow[lane + 32];
    float4 b0 = reinterpret_cast<const float4*>(be)[lane];
    float4 b1 = reinterpret_cast<const float4*>(be)[lane + 32];
    float4 o0, o1;
    o0.x = lrelu(acc0.x + rt0.x + b0.x); o0.y = lrelu(acc0.y + rt0.y + b0.y);
    o0.z = lrelu(acc0.z + rt0.z + b0.z); o0.w = lrelu(acc0.w + rt0.w + b0.w);
    o1.x = lrelu(acc1.x + rt1.x + b1.x); o1.y = lrelu(acc1.y + rt1.y + b1.y);
    o1.z = lrelu(acc1.z + rt1.z + b1.z); o1.w = lrelu(acc1.w + rt1.w + b1.w);
    float4* lrow = reinterpret_cast<float4*>(lat) + (size_t)node * 64;
    lrow[lane] = o0;
    lrow[lane + 32] = o1;
    uint32_t* oh32 = reinterpret_cast<uint32_t*>(lath) + (size_t)node * 128;
    uint32_t* ol32 = reinterpret_cast<uint32_t*>(latl) + (size_t)node * 128;
    {
        float h0 = bf_round(o0.x), h1 = bf_round(o0.y), h2 = bf_round(o0.z), h3 = bf_round(o0.w);
        oh32[lane * 2]     = pack_bf16(h0, h1);
        oh32[lane * 2 + 1] = pack_bf16(h2, h3);
        ol32[lane * 2]     = pack_bf16(o0.x - h0, o0.y - h1);
        ol32[lane * 2 + 1] = pack_bf16(o0.z - h2, o0.w - h3);
        float g0 = bf_round(o1.x), g1 = bf_round(o1.y), g2 = bf_round(o1.z), g3 = bf_round(o1.w);
        oh32[(lane + 32) * 2]     = pack_bf16(g0, g1);
        oh32[(lane + 32) * 2 + 1] = pack_bf16(g2, g3);
        ol32[(lane + 32) * 2]     = pack_bf16(o1.x - g0, o1.y - g1);
        ol32[(lane + 32) * 2 + 1] = pack_bf16(o1.z - g2, o1.w - g3);
    }
    int g = batch[node];
    float4* prow = reinterpret_cast<float4*>(pooled) + (size_t)g * 64;
    red_add_v4(prow + lane, o0);
    red_add_v4(prow + lane + 32, o1);
}

// ---------------- CSR gather (warp per node), C=256 -> hi/lo ----------------------
__global__ void __launch_bounds__(256)
gather_c256(const float* __restrict__ xin,
            __nv_bfloat16* __restrict__ oh, __nv_bfloat16* __restrict__ ol,
            const int* __restrict__ rowptr, const int* __restrict__ esrc) {
    int node = (blockIdx.x * blockDim.x + threadIdx.x) >> 5;
    int lane = threadIdx.x & 31;
    if (node >= N_NODES) return;
    int bg = rowptr[node], en = rowptr[node + 1];
    float4 acc0 = make_float4(0.f, 0.f, 0.f, 0.f);
    float4 acc1 = make_float4(0.f, 0.f, 0.f, 0.f);
#pragma unroll 2
    for (int j = bg; j < en; j++) {
        int s = esrc[j];
        const float4* row = reinterpret_cast<const float4*>(xin) + (size_t)s * 64;
        float4 v0 = row[lane];
        float4 v1 = row[lane + 32];
        acc0.x += v0.x; acc0.y += v0.y; acc0.z += v0.z; acc0.w += v0.w;
        acc1.x += v1.x; acc1.y += v1.y; acc1.z += v1.z; acc1.w += v1.w;
    }
    uint32_t* oh32 = reinterpret_cast<uint32_t*>(oh) + (size_t)node * 128;
    uint32_t* ol32 = reinterpret_cast<uint32_t*>(ol) + (size_t)node * 128;
    float h0 = bf_round(acc0.x), h1 = bf_round(acc0.y), h2 = bf_round(acc0.z), h3 = bf_round(acc0.w);
    oh32[lane * 2]     = pack_bf16(h0, h1);
    oh32[lane * 2 + 1] = pack_bf16(h2, h3);
    ol32[lane * 2]     = pack_bf16(acc0.x - h0, acc0.y - h1);
    ol32[lane * 2 + 1] = pack_bf16(acc0.z - h2, acc0.w - h3);
    float g0 = bf_round(acc1.x), g1 = bf_round(acc1.y), g2 = bf_round(acc1.z), g3 = bf_round(acc1.w);
    oh32[(lane + 32) * 2]     = pack_bf16(g0, g1);
    oh32[(lane + 32) * 2 + 1] = pack_bf16(g2, g3);
    ol32[(lane + 32) * 2]     = pack_bf16(acc1.x - g0, acc1.y - g1);
    ol32[(lane + 32) * 2 + 1] = pack_bf16(acc1.z - g2, acc1.w - g3);
}

// ---------------- transpose + hi/lo split (paired) --------------------------------
__global__ void transpose_split2(const float* __restrict__ W1, __nv_bfloat16* __restrict__ oh1,
                                 __nv_bfloat16* __restrict__ ol1,
                                 const float* __restrict__ W2, __nv_bfloat16* __restrict__ oh2,
                                 __nv_bfloat16* __restrict__ ol2, int K, int N) {
    const float* W = blockIdx.z ? W2 : W1;
    __nv_bfloat16* oh = blockIdx.z ? oh2 : oh1;
    __nv_bfloat16* ol = blockIdx.z ? ol2 : ol1;
    __shared__ float tile[32][33];
    int n0 = blockIdx.x * 32, k0 = blockIdx.y * 32;
    int tx = threadIdx.x, ty = threadIdx.y;
#pragma unroll
    for (int j = 0; j < 32; j += 8)
        tile[ty + j][tx] = W[(size_t)(k0 + ty + j) * N + n0 + tx];
    __syncthreads();
#pragma unroll
    for (int j = 0; j < 32; j += 8) {
        float v = tile[tx][ty + j];
        float h = bf_round(v);
        size_t o = (size_t)(n0 + ty + j) * K + k0 + tx;
        oh[o] = __float2bfloat16(h);
        ol[o] = __float2bfloat16(v - h);
    }
}

// ---------------- 3-stage cp.async pre-split bf16 GEMM (XOR-swizzled) -------------
#define OFF_AL   8192            // 128 rows * 64 B
#define OFF_BH   16384
#define OFF_BL   24576
#define STAGE_B  32768
#define GEMM_SMEM (3 * STAGE_B)  // 98304; 2 CTAs/SM = 196608

__global__ void __launch_bounds__(512, 2)
gemm_split(const __nv_bfloat16* __restrict__ A1h, const __nv_bfloat16* __restrict__ A1l, int K1,
           const __nv_bfloat16* __restrict__ A2h, const __nv_bfloat16* __restrict__ A2l, int K2,
           const __nv_bfloat16* __restrict__ W1h, const __nv_bfloat16* __restrict__ W1l,
           const __nv_bfloat16* __restrict__ W2h, const __nv_bfloat16* __restrict__ W2l,
           const float* __restrict__ add, const float* __restrict__ bias,
           float* __restrict__ C, __nv_bfloat16* __restrict__ Ch,
           __nv_bfloat16* __restrict__ Cl, int M, int N, int leaky) {
    extern __shared__ __align__(16) char smc[];
    int tid = threadIdx.x;
    int lane = tid & 31, wid = tid >> 5;
    int wm = (wid & 3) * 32;
    int wn = (wid >> 2) * 32;
    int brow = blockIdx.y * 128;
    int bcol = blockIdx.x * 128;
    uint32_t sbase = (uint32_t)__cvta_generic_to_shared(smc);

    float acc[2][4][4];
#pragma unroll
    for (int mt = 0; mt < 2; mt++)
#pragma unroll
        for (int nt = 0; nt < 4; nt++)
#pragma unroll
            for (int r = 0; r < 4; r++) acc[mt][nt][r] = 0.f;

    int T1 = A1h ? (K1 / 32) : 0;
    int T2 = A2h ? (K2 / 32) : 0;
    int T = T1 + T2;

    int srow = tid >> 2;
    int sc   = tid & 3;
    uint32_t sphys = srow * 64 + ((sc ^ ((srow >> 1) & 3)) << 4);

    int lr = lane & 7;
    uint32_t a_row[2]; int qa[2];
#pragma unroll
    for (int mt = 0; mt < 2; mt++) {
        int row = wm + mt * 16 + ((lane >> 3) & 1) * 8 + lr;
        a_row[mt] = row * 64;
        qa[mt] = (row >> 1) & 3;
    }
    uint32_t b_row[2]; int qb[2];
#pragma unroll
    for (int p = 0; p < 2; p++) {
        int n = wn + p * 16 + (lane >> 4) * 8 + lr;
        b_row[p] = n * 64;
        qb[p] = (n >> 1) & 3;
    }
    int ca = lane >> 4;
    int cb = (lane >> 3) & 1;

    auto issue = [&](int t, int stage) {
        const __nv_bfloat16 *Ah, *Al, *Wh, *Wl; int K, k0;
        if (t < T1) { Ah = A1h; Al = A1l; Wh = W1h; Wl = W1l; K = K1; k0 = t * 32; }
        else        { Ah = A2h; Al = A2l; Wh = W2h; Wl = W2l; K = K2; k0 = (t - T1) * 32; }
        uint32_t sb = sbase + stage * STAGE_B;
        size_t go = (size_t)(brow + srow) * K + k0 + sc * 8;
        cp16(sb + sphys, Ah + go);
        cp16(sb + OFF_AL + sphys, Al + go);
        size_t gb = (size_t)(bcol + srow) * K + k0 + sc * 8;
        cp16(sb + OFF_BH + sphys, Wh + gb);
        cp16(sb + OFF_BL + sphys, Wl + gb);
        cp_commit();
    };

    auto compute = [&](int stage) {
        uint32_t sb = sbase + stage * STAGE_B;
#pragma unroll
        for (int ks = 0; ks < 2; ks++) {
            uint32_t aH[2][4], aL[2][4], bH[4][2], bL[4][2];
#pragma unroll
            for (int mt = 0; mt < 2; mt++) {
                uint32_t off = a_row[mt] + ((((ks << 1) | ca) ^ qa[mt]) << 4);
                ldsm4(aH[mt], sb + off);
                ldsm4(aL[mt], sb + OFF_AL + off);
            }
#pragma unroll
            for (int p = 0; p < 2; p++) {
                uint32_t off = b_row[p] + ((((ks << 1) | cb) ^ qb[p]) << 4);
                ldsm4(&bH[p * 2][0], sb + OFF_BH + off);
                ldsm4(&bL[p * 2][0], sb + OFF_BL + off);
            }
#pragma unroll
            for (int mt = 0; mt < 2; mt++)
#pragma unroll
                for (int nt = 0; nt < 4; nt++) {
                    mma_bf16(acc[mt][nt], aH[mt], bH[nt]);
                    mma_bf16(acc[mt][nt], aH[mt], bL[nt]);
                    mma_bf16(acc[mt][nt], aL[mt], bH[nt]);
                }
        }
    };

    // ---- 3-stage ring, 2 chunks in flight, one sync per chunk ----
#pragma unroll
    for (int i = 0; i < 2; i++) {
        if (i < T) issue(i, i);
        else cp_commit();
    }
#pragma unroll 1
    for (int t = 0; t < T; t++) {
        cp_wait<1>();
        __syncthreads();
        if (t + 2 < T) issue(t + 2, (t + 2) % 3);
        else cp_commit();
        compute(t % 3);
    }

    // ---- epilogue ----
#pragma unroll
    for (int mt = 0; mt < 2; mt++) {
#pragma unroll
        for (int nt = 0; nt < 4; nt++) {
            int r0 = brow + wm + mt * 16 + (lane >> 2);
            int c  = bcol + wn + nt * 8 + (lane & 3) * 2;
#pragma unroll
            for (int half = 0; half < 2; half++) {
                int row = r0 + half * 8;
                if (row >= M) continue;
                float v0 = acc[mt][nt][half * 2 + 0];
                float v1 = acc[mt][nt][half * 2 + 1];
                if (add) {
                    const float2 a2 = *reinterpret_cast<const float2*>(add + (size_t)row * N + c);
                    v0 += a2.x; v1 += a2.y;
                }
                if (bias) {
                    const float2 b2 = *reinterpret_cast<const float2*>(bias + c);
                    v0 += b2.x; v1 += b2.y;
                }
                if (leaky) { v0 = lrelu(v0); v1 = lrelu(v1); }
                *reinterpret_cast<float2*>(C + (size_t)row * N + c) = make_float2(v0, v1);
                if (Ch) {
                    float h0 = bf_round(v0), h1f = bf_round(v1);
                    *reinterpret_cast<uint32_t*>(Ch + (size_t)row * N + c) = pack_bf16(h0, h1f);
                    *reinterpret_cast<uint32_t*>(Cl + (size_t)row * N + c) = pack_bf16(v0 - h0, v1 - h1f);
                }
            }
        }
    }
}

// ---------------- logits ----------------------------------------------------------
__global__ void logits_kernel(const float* __restrict__ pooled, const float* __restrict__ counts,
                              const float* __restrict__ w_lin, const float* __restrict__ b_lin,
                              float* __restrict__ out) {
    int g = blockIdx.x;
    int o = threadIdx.x;
    if (o >= OUT_CLS) return;
    float inv = 1.0f / fmaxf(counts[g], 1.0f);
    float s = 0.f;
    const float* pr = pooled + g * 256;
    for (int k = 0; k < 256; k++) s += pr[k] * w_lin[k * OUT_CLS + o];
    out[g * OUT_CLS + o] = s * inv + b_lin[o];
}

// ---------------- host launch -----------------------------------------------------
extern "C" void kernel_launch(void* const* d_in, const int* in_sizes, int n_in,
                              void* d_out, int out_size) {
    const int*   x       = (const int*)d_in[0];
    const int*   ei      = (const int*)d_in[1];
    const int*   batch   = (const int*)d_in[2];
    const float* emb     = (const float*)d_in[3];
    const float* w1_rel  = (const float*)d_in[4];
    const float* w1_root = (const float*)d_in[5];
    const float* b1      = (const float*)d_in[6];
    const float* w2_rel  = (const float*)d_in[7];
    const float* w2_root = (const float*)d_in[8];
    const float* b2      = (const float*)d_in[9];
    const float* we_rel  = (const float*)d_in[10];
    const float* we_root = (const float*)d_in[11];
    const float* be      = (const float*)d_in[12];
    const float* wd_rel  = (const float*)d_in[13];
    const float* wd_root = (const float*)d_in[14];
    const float* bd      = (const float*)d_in[15];
    const float* w_lin   = (const float*)d_in[16];
    const float* b_lin   = (const float*)d_in[17];

    const int* src = ei;
    const int* dst = ei + N_EDGES;

    float* out    = (float*)d_out;
    float* logits = out;
    float* recon  = out + OFF_RECON;
    float* orig   = out + OFF_ORIG;

    float *h1, *bufE, *lat, *pool, *cnt;
    int *deg, *rowptr, *posn, *esrc, *part;
    cudaGetSymbolAddress((void**)&h1,    g_h1);
    cudaGetSymbolAddress((void**)&bufE,  g_enc);
    cudaGetSymbolAddress((void**)&lat,   g_lat);
    cudaGetSymbolAddress((void**)&pool,  g_pool);
    cudaGetSymbolAddress((void**)&cnt,   g_cnt);
    cudaGetSymbolAddress((void**)&deg,   g_deg);
    cudaGetSymbolAddress((void**)&rowptr,g_rowptr);
    cudaGetSymbolAddress((void**)&posn,  g_posn);
    cudaGetSymbolAddress((void**)&esrc,  g_esrc);
    cudaGetSymbolAddress((void**)&part,  g_part);

    __nv_bfloat16 *h1h,*h1l,*a1h,*a1l,*oh,*ol,*lath,*latl,*aggh,*aggl;
    __nv_bfloat16 *w2rh,*w2rl,*w2oh,*w2ol,*wcath,*wcatl,*wdrh,*wdrl,*wdoh,*wdol;
    cudaGetSymbolAddress((void**)&h1h, g_h1h);   cudaGetSymbolAddress((void**)&h1l, g_h1l);
    cudaGetSymbolAddress((void**)&a1h, g_a1h);   cudaGetSymbolAddress((void**)&a1l, g_a1l);
    cudaGetSymbolAddress((void**)&oh,  g_oh);    cudaGetSymbolAddress((void**)&ol,  g_ol);
    cudaGetSymbolAddress((void**)&lath,g_lath);  cudaGetSymbolAddress((void**)&latl,g_latl);
    cudaGetSymbolAddress((void**)&aggh,g_aggh);  cudaGetSymbolAddress((void**)&aggl,g_aggl);
    cudaGetSymbolAddress((void**)&w2rh,g_w2r_h); cudaGetSymbolAddress((void**)&w2rl,g_w2r_l);
    cudaGetSymbolAddress((void**)&w2oh,g_w2o_h); cudaGetSymbolAddress((void**)&w2ol,g_w2o_l);
    cudaGetSymbolAddress((void**)&wcath,g_wcat_h); cudaGetSymbolAddress((void**)&wcatl,g_wcat_l);
    cudaGetSymbolAddress((void**)&wdrh,g_wdr_h); cudaGetSymbolAddress((void**)&wdrl,g_wdr_l);
    cudaGetSymbolAddress((void**)&wdoh,g_wdo_h); cudaGetSymbolAddress((void**)&wdol,g_wdo_l);

    cudaFuncSetAttribute(gemm_split, cudaFuncAttributeMaxDynamicSharedMemorySize, GEMM_SMEM);

    // CSR build
    zero_misc<<<256, 256>>>(deg, pool, cnt);
    hist_kernel<<<(N_EDGES + 255) / 256, 256>>>(dst, deg, batch, cnt);
    scan_local<<<SCAN_BLOCKS, 1024>>>(deg, rowptr, part);
    scan_partials<<<1, 64>>>(part);
    scan_add<<<(N_NODES + 255) / 256, 256>>>(rowptr, part, posn);
    scatter_kernel<<<(N_EDGES + 255) / 256, 256>>>(src, dst, posn, esrc);

    // fused conv1
    conv1_fused<<<(N_NODES + 7) / 8, 256>>>(x, emb, rowptr, esrc,
                                            w1_rel, w1_root, b1, h1, h1h, h1l);

    // 64-wide gather (h1 -> aggr hi/lo)
    gather_h16<<<(N_NODES * 16 + 255) / 256, 256>>>(h1, a1h, a1l, rowptr, esrc);

    // w2 transposes (paired)
    {
        dim3 b(32, 8);
        transpose_split2<<<dim3(1024/32, 64/32, 2), b>>>(w2_rel, w2rh, w2rl,
                                                         w2_root, w2oh, w2ol, 64, 1024);
    }
    // conv2 GEMM -> orig (+hi/lo)
    {
        dim3 grid(1024 / 128, (N_NODES + 127) / 128);
        gemm_split<<<grid, 512, GEMM_SMEM>>>(a1h, a1l, 64, h1h, h1l, 64,
                                             w2rh, w2rl, w2oh, w2ol,
                                             nullptr, b2, orig, oh, ol, N_NODES, 1024, 1);
    }

    // we transposes (paired) -> concatenated [512][1024]
    {
        dim3 b(32, 8);
        transpose_split2<<<dim3(256/32, 1024/32, 2), b>>>(we_rel, wcath, wcatl,
                                                          we_root, wcath + 256 * 1024,
                                                          wcatl + 256 * 1024, 1024, 256);
    }
    // fused enc GEMM (N=512): bufE = [orig@we_rel | orig@we_root]
    {
        dim3 grid(512 / 128, (N_NODES + 127) / 128);
        gemm_split<<<grid, 512, GEMM_SMEM>>>(oh, ol, 1024, nullptr, nullptr, 0,
                                             wcath, wcatl, nullptr, nullptr,
                                             nullptr, nullptr, bufE, nullptr, nullptr,
                                             N_NODES, 512, 0);
    }
    // enc finish (warp/node): gather rel + root + bias + leaky -> lat (+hi/lo) + pool
    gather_enc_fin<<<(N_NODES * 32 + 255) / 256, 256>>>(bufE, be, lat, lath, latl,
                                                        rowptr, esrc, batch, pool);

    // 256-wide gather (warp/node) lat -> agg hi/lo
    gather_c256<<<(N_NODES * 32 + 255) / 256, 256>>>(lat, aggh, aggl, rowptr, esrc);

    // logits
    logits_kernel<<<N_GRAPHS, 32>>>(pool, cnt, w_lin, b_lin, logits);

    // wd transposes (paired)
    {
        dim3 b(32, 8);
        transpose_split2<<<dim3(1024/32, 256/32, 2), b>>>(wd_rel, wdrh, wdrl,
                                                          wd_root, wdoh, wdol, 256, 1024);
    }
    // dec GEMM -> recon
    {
        dim3 grid(1024 / 128, (N_NODES + 127) / 128);
        gemm_split<<<grid, 512, GEMM_SMEM>>>(aggh, aggl, 256, lath, latl, 256,
                                             wdrh, wdrl, wdoh, wdol,
                                             nullptr, bd, recon, nullptr, nullptr,
                                             N_NODES, 1024, 1);
    }
}